// round 10
// baseline (speedup 1.0000x reference)
#include <cuda_runtime.h>
#include <stdint.h>

// Binarized depthwise 3x3 conv, stride 1, SAME. x:(16,112,112,256) NHWC fp32,
// kernel:(3,3,256,1). out = sum of sign(x)*sign(k) over valid taps.
//
// TWO-PASS, stream-purity design. R2-R9 showed a hard ~5.7 TB/s plateau for
// the fused kernel = mixed 50/50 read/write HBM efficiency. Split:
//   Pass 1 (read-pure):  x (205 MB) -> 1 sign bit/elem, packed 6.4 MB scratch
//                        (ballot_sync across lanes = 32 channels/word).
//   Pass 2 (write-pure): packed bits (L2-resident) -> rebuild bf16x2 sign
//                        carriers -> LOP3+HADD2 column recurrence -> out.
//
// bf16x2 math (exact, |sum|<=9): per tap, product = (t & 0x80008000) ^ kp
// where t carries sign bits at 15/31 and kp is bf16x2 of +-1.0 (0 for
// missing border rows -> +-0.0 adds as no-op).

#define NN 16
#define HH 112
#define WW 112
#define CC 256
#define W8 (WW * 8)             // packed words per (n,h) row

// Packed signs: [n][h][w][c32], bit l of word = sign(x[ch = c32*32 + l]) < 0.
__device__ uint32_t g_packed[(size_t)NN * HH * WW * 8];

// ---------------- Pass 1: sign-pack (read-pure) ----------------
__global__ __launch_bounds__(256, 8)
void pack_kernel(const float* __restrict__ x) {
    const int h = blockIdx.x;
    const int n = blockIdx.y;
    const int lane = threadIdx.x & 31;
    const int c32 = threadIdx.x >> 5;       // 8 warps = 8 channel groups

    const float* px = x + (((size_t)n * HH + h) * WW) * CC + c32 * 32 + lane;
    uint32_t* po = g_packed + (((size_t)n * HH + h) * WW) * 8 + c32;

    for (int wb = 0; wb < WW; wb += 32) {
        uint32_t myword = 0;
#pragma unroll
        for (int i = 0; i < 32; ++i) {
            const float v = px[(size_t)(wb + i) * CC];
            const uint32_t b = __ballot_sync(0xFFFFFFFFu, v < 0.0f);
            if (lane == i) myword = b;
        }
        po[(size_t)(wb + lane) * 8] = myword;
    }
}

// ---------------- Pass 2: conv from bits (write-pure) ----------------
__device__ __forceinline__ uint32_t badd(uint32_t a, uint32_t b) {
    uint32_t r;
    asm("add.rn.bf16x2 %0, %1, %2;" : "=r"(r) : "r"(a), "r"(b));
    return r;
}

#define TAPP(t, kp) ((((t) & 0x80008000u)) ^ (kp))

// From packed word p, channel-nibble shift j: build two bf16x2 sign carriers
// (a: channels j,j+1 ; b: channels j+2,j+3), sign bits at positions 15/31.
__device__ __forceinline__ void carriers(uint32_t p, int j,
                                         uint32_t& a, uint32_t& b) {
    const uint32_t u = p >> j;
    a = ((u << 15) & 0x8000u) | ((u << 30) & 0x80000000u);
    b = ((u << 13) & 0x8000u) | ((u << 28) & 0x80000000u);
}

__device__ __forceinline__ void store4(float* __restrict__ p,
                                       uint32_t oa, uint32_t ob) {
    float4 o4;
    o4.x = __uint_as_float(oa << 16);
    o4.y = __uint_as_float(oa & 0xFFFF0000u);
    o4.z = __uint_as_float(ob << 16);
    o4.w = __uint_as_float(ob & 0xFFFF0000u);
    *reinterpret_cast<float4*>(p) = o4;
}

__global__ __launch_bounds__(256, 4)
void conv_kernel(const float* __restrict__ k, float* __restrict__ out) {
    const int h = blockIdx.x;
    const int n = blockIdx.y;
    const int t = threadIdx.x;
    const int quad = t & 63;                // 4 channels: c0 = quad*4
    const int strip = t >> 6;               // 4 strips of 28 columns
    const int c0 = quad * 4;
    const int j = (quad & 7) * 4;           // bit offset within packed word

    const bool hasT = (h > 0);
    const bool hasB = (h < HH - 1);

    // Kernel signs as bf16x2 of +-1.0 per channel pair; halves a(ch0/1), b(ch2/3).
    uint32_t kp[3][3][2];
#pragma unroll
    for (int kh = 0; kh < 3; ++kh) {
        const bool rv = (kh == 0) ? hasT : ((kh == 2) ? hasB : true);
#pragma unroll
        for (int kw = 0; kw < 3; ++kw) {
            const float4 kv = *reinterpret_cast<const float4*>(k + (kh * 3 + kw) * CC + c0);
            uint32_t s0 = (kv.x >= 0.0f) ? 0x3F80u : 0xBF80u;
            uint32_t s1 = (kv.y >= 0.0f) ? 0x3F80u : 0xBF80u;
            uint32_t s2 = (kv.z >= 0.0f) ? 0x3F80u : 0xBF80u;
            uint32_t s3 = (kv.w >= 0.0f) ? 0x3F80u : 0xBF80u;
            kp[kh][kw][0] = rv ? (s0 | (s1 << 16)) : 0u;
            kp[kh][kw][1] = rv ? (s2 | (s3 << 16)) : 0u;
        }
    }

    // Packed-word row pointers (stride W8 words per image row); clamped rows
    // contribute +-0.0 via zeroed kp.
    const uint32_t* p1 = g_packed + (((size_t)n * HH + h) * WW) * 8 + (quad >> 3);
    const uint32_t* p0 = hasT ? p1 - W8 : p1;
    const uint32_t* p2 = hasB ? p1 + W8 : p1;
    float* o = out + (((size_t)n * HH + h) * WW) * CC + c0;

    const int ws = strip * (WW / 4);
    const int we = ws + (WW / 4);
    const int cbeg = (ws == 0) ? 0 : ws - 1;
    const int cend = (we == WW) ? WW - 1 : we;

    uint32_t Aa, Ab, Ba, Bb;

    // ---- peeled first column (no store) ----
    {
        uint32_t t0a, t0b, t1a, t1b, t2a, t2b;
        carriers(p0[(size_t)cbeg * 8], j, t0a, t0b);
        carriers(p1[(size_t)cbeg * 8], j, t1a, t1b);
        carriers(p2[(size_t)cbeg * 8], j, t2a, t2b);
        Ba = badd(badd(TAPP(t0a, kp[0][0][0]), TAPP(t1a, kp[1][0][0])), TAPP(t2a, kp[2][0][0]));
        Bb = badd(badd(TAPP(t0b, kp[0][0][1]), TAPP(t1b, kp[1][0][1])), TAPP(t2b, kp[2][0][1]));
        Aa = badd(badd(TAPP(t0a, kp[0][1][0]), TAPP(t1a, kp[1][1][0])), TAPP(t2a, kp[2][1][0]));
        Ab = badd(badd(TAPP(t0b, kp[0][1][1]), TAPP(t1b, kp[1][1][1])), TAPP(t2b, kp[2][1][1]));
    }

    // ---- branchless main loop: load col c, store col c-1 ----
#pragma unroll 4
    for (int c = cbeg + 1; c <= cend; ++c) {
        uint32_t t0a, t0b, t1a, t1b, t2a, t2b;
        carriers(p0[(size_t)c * 8], j, t0a, t0b);
        carriers(p1[(size_t)c * 8], j, t1a, t1b);
        carriers(p2[(size_t)c * 8], j, t2a, t2b);

        const uint32_t q0a = badd(badd(TAPP(t0a, kp[0][0][0]), TAPP(t1a, kp[1][0][0])), TAPP(t2a, kp[2][0][0]));
        const uint32_t q0b = badd(badd(TAPP(t0b, kp[0][0][1]), TAPP(t1b, kp[1][0][1])), TAPP(t2b, kp[2][0][1]));
        const uint32_t q1a = badd(badd(TAPP(t0a, kp[0][1][0]), TAPP(t1a, kp[1][1][0])), TAPP(t2a, kp[2][1][0]));
        const uint32_t q1b = badd(badd(TAPP(t0b, kp[0][1][1]), TAPP(t1b, kp[1][1][1])), TAPP(t2b, kp[2][1][1]));
        const uint32_t q2a = badd(badd(TAPP(t0a, kp[0][2][0]), TAPP(t1a, kp[1][2][0])), TAPP(t2a, kp[2][2][0]));
        const uint32_t q2b = badd(badd(TAPP(t0b, kp[0][2][1]), TAPP(t1b, kp[1][2][1])), TAPP(t2b, kp[2][2][1]));

        store4(o + (size_t)(c - 1) * CC, badd(Aa, q2a), badd(Ab, q2b));
        Aa = badd(Ba, q1a); Ba = q0a;
        Ab = badd(Bb, q1b); Bb = q0b;
    }

    if (we == WW) {  // right border: out[111] = q0(110) + q1(111) = A
        store4(o + (size_t)(WW - 1) * CC, Aa, Ab);
    }
}

extern "C" void kernel_launch(void* const* d_in, const int* in_sizes, int n_in,
                              void* d_out, int out_size) {
    const float* x = (const float*)d_in[0];
    const float* k = (const float*)d_in[1];
    float* out = (float*)d_out;
    dim3 grid(HH, NN);
    pack_kernel<<<grid, 256>>>(x);
    conv_kernel<<<grid, 256>>>(k, out);
}